// round 12
// baseline (speedup 1.0000x reference)
#include <cuda_runtime.h>
#include <cuda_bf16.h>
#include <cstdint>
#include <math.h>

#define B_    16
#define N_    8192
#define C_    256
#define HID_  128
#define KEEP_ 5734
#define M_    (B_*N_)   // 131072 rows
#define FT    512       // fused kernel threads
#define NWARP (FT/32)   // 16
#define NBIN  4096
#define BANDCAP  1024
#define MICROCAP 128
#define KLCAP    1024

// ---------------- scratch (device globals; no allocation allowed) ----------
__device__ float g_scores[M_];
__device__ int   g_idx[B_*KEEP_];
// W1 fragments, mma.m16n8k16 B-operand layout:
// hi-only (screen): [kt][nt][lane] uint2 ; hi+lo (refine): uint4
__device__ __align__(16) uint2 g_w1fragH[16*16*32];
__device__ __align__(16) uint4 g_w1frag4[16*16*32];

// ---------------- helpers ---------------------------------------------------
__device__ __forceinline__ uint32_t pack2(__nv_bfloat16 lo, __nv_bfloat16 hi) {
    uint16_t a = __bfloat16_as_ushort(lo);
    uint16_t b = __bfloat16_as_ushort(hi);
    return ((uint32_t)b << 16) | (uint32_t)a;
}
__device__ __forceinline__ uint32_t cvt2(float2 f) {
    __nv_bfloat162 h = __float22bfloat162_rn(f);
    return *(uint32_t*)&h;
}
__device__ __forceinline__ uint32_t split2(float2 f, uint32_t& lo) {
    __nv_bfloat16 hx = __float2bfloat16_rn(f.x);
    __nv_bfloat16 hy = __float2bfloat16_rn(f.y);
    lo = pack2(__float2bfloat16_rn(f.x - __bfloat162float(hx)),
               __float2bfloat16_rn(f.y - __bfloat162float(hy)));
    return pack2(hx, hy);
}
__device__ __forceinline__ void mma16816(float* c, const uint32_t* a,
                                         uint32_t b0, uint32_t b1) {
    asm volatile(
        "mma.sync.aligned.m16n8k16.row.col.f32.bf16.bf16.f32 "
        "{%0,%1,%2,%3},{%4,%5,%6,%7},{%8,%9},{%0,%1,%2,%3};\n"
        : "+f"(c[0]), "+f"(c[1]), "+f"(c[2]), "+f"(c[3])
        : "r"(a[0]), "r"(a[1]), "r"(a[2]), "r"(a[3]), "r"(b0), "r"(b1));
}
__device__ __forceinline__ float gelu_exact(float x) {
    return 0.5f * x * (1.0f + erff(x * 0.70710678118654752f));
}
__device__ __forceinline__ uint32_t fmap(float f) {
    uint32_t v = __float_as_uint(f);
    return (v & 0x80000000u) ? ~v : (v | 0x80000000u);
}
__device__ __forceinline__ float funmap(uint32_t k) {
    return (k & 0x80000000u) ? __uint_as_float(k ^ 0x80000000u)
                             : __uint_as_float(~k);
}
__device__ __forceinline__ int binof(float s, float lo, float invw) {
    int b = (int)((s - lo) * invw);
    return min(max(b, 0), NBIN - 1);
}

// ---------------- kernel 1: pack W1 into bf16 mma fragments ----------------
__global__ void prep_w1(const float* __restrict__ W1) {
    int id = blockIdx.x * blockDim.x + threadIdx.x;   // 8192 total
    if (id >= 16*16*32) return;
    int lane = id & 31;
    int kt   = id >> 9;
    int t = lane & 3, g = lane >> 2;
    int nt = (id >> 5) & 15;
    int n  = nt*8 + g;
    int k0 = kt*16 + t*2;
    float w00 = W1[k0*HID_ + n],     w01 = W1[(k0+1)*HID_ + n];
    float w10 = W1[(k0+8)*HID_ + n], w11 = W1[(k0+9)*HID_ + n];
    __nv_bfloat16 h00 = __float2bfloat16_rn(w00), h01 = __float2bfloat16_rn(w01);
    __nv_bfloat16 h10 = __float2bfloat16_rn(w10), h11 = __float2bfloat16_rn(w11);
    uint4 v;
    v.x = pack2(h00, h01);
    v.y = pack2(h10, h11);
    v.z = pack2(__float2bfloat16_rn(w00 - __bfloat162float(h00)),
                __float2bfloat16_rn(w01 - __bfloat162float(h01)));
    v.w = pack2(__float2bfloat16_rn(w10 - __bfloat162float(h10)),
                __float2bfloat16_rn(w11 - __bfloat162float(h11)));
    g_w1frag4[id] = v;
    g_w1fragH[id] = make_uint2(v.x, v.y);
}

// ---------------- kernel 2: screen: fc1(bf16 mma) -> GELU -> fc2 -----------
// 32 rows per warp (2 m-tiles): B-fragment loads amortized 2x; A loads for
// kt+1 prefetched into registers while kt's 32 HMMAs issue.
__global__ void __launch_bounds__(256, 1)
gemm_scores(const float* __restrict__ tokens,
            const float* __restrict__ b1,
            const float* __restrict__ W2) {
    __shared__ float s_b1[HID_], s_w2[HID_];
    const int tid = threadIdx.x;
    if (tid < HID_) { s_b1[tid] = b1[tid]; s_w2[tid] = W2[tid]; }
    __syncthreads();

    const int warp = tid >> 5, lane = tid & 31;
    const int g = lane >> 2, t = lane & 3;
    const long long row0 = (long long)(blockIdx.x * 8 + warp) * 32;
    const float* A0 = tokens + row0 * C_;

    float acc[2][16][4];
    #pragma unroll
    for (int m = 0; m < 2; m++)
        #pragma unroll
        for (int n = 0; n < 16; n++)
            #pragma unroll
            for (int q = 0; q < 4; q++) acc[m][n][q] = 0.0f;

    const uint2* Bf = g_w1fragH + lane;

    float2 f[2][4];
    {   // prefetch kt = 0
        const int col = t*2;
        #pragma unroll
        for (int mt = 0; mt < 2; mt++) {
            const float* Ar = A0 + mt*16*C_;
            f[mt][0] = *(const float2*)(Ar + (g)     * C_ + col);
            f[mt][1] = *(const float2*)(Ar + (g + 8) * C_ + col);
            f[mt][2] = *(const float2*)(Ar + (g)     * C_ + col + 8);
            f[mt][3] = *(const float2*)(Ar + (g + 8) * C_ + col + 8);
        }
    }

    #pragma unroll
    for (int kt = 0; kt < 16; kt++) {
        uint32_t a[2][4];
        #pragma unroll
        for (int mt = 0; mt < 2; mt++)
            #pragma unroll
            for (int q = 0; q < 4; q++) a[mt][q] = cvt2(f[mt][q]);

        if (kt < 15) {   // prefetch kt+1
            const int col = (kt+1)*16 + t*2;
            #pragma unroll
            for (int mt = 0; mt < 2; mt++) {
                const float* Ar = A0 + mt*16*C_;
                f[mt][0] = *(const float2*)(Ar + (g)     * C_ + col);
                f[mt][1] = *(const float2*)(Ar + (g + 8) * C_ + col);
                f[mt][2] = *(const float2*)(Ar + (g)     * C_ + col + 8);
                f[mt][3] = *(const float2*)(Ar + (g + 8) * C_ + col + 8);
            }
        }

        const uint2* bp = Bf + kt*16*32;
        #pragma unroll
        for (int nt = 0; nt < 16; nt++) {
            uint2 bb = bp[nt*32];
            mma16816(acc[0][nt], a[0], bb.x, bb.y);
            mma16816(acc[1][nt], a[1], bb.x, bb.y);
        }
    }

    #pragma unroll
    for (int mt = 0; mt < 2; mt++) {
        float p0 = 0.0f, p1 = 0.0f;
        #pragma unroll
        for (int nt = 0; nt < 16; nt++) {
            int c0 = nt*8 + t*2, c1 = c0 + 1;
            p0 += gelu_exact(acc[mt][nt][0] + s_b1[c0]) * s_w2[c0];
            p0 += gelu_exact(acc[mt][nt][1] + s_b1[c1]) * s_w2[c1];
            p1 += gelu_exact(acc[mt][nt][2] + s_b1[c0]) * s_w2[c0];
            p1 += gelu_exact(acc[mt][nt][3] + s_b1[c1]) * s_w2[c1];
        }
        p0 += __shfl_xor_sync(0xffffffffu, p0, 1);
        p0 += __shfl_xor_sync(0xffffffffu, p0, 2);
        p1 += __shfl_xor_sync(0xffffffffu, p1, 1);
        p1 += __shfl_xor_sync(0xffffffffu, p1, 2);
        if (t == 0) {
            g_scores[row0 + mt*16 + g]     = p0;
            g_scores[row0 + mt*16 + 8 + g] = p1;
        }
    }
}

// ---------------- exact K-th select via linear histogram + small-set -------
__device__ void exact_sel(const float* sx, int* hist, int* sw, uint32_t* klist,
                          int* sci, float lo, float invw, int K) {
    const int tid = threadIdx.x, warp = tid >> 5, lane = tid & 31;
    for (int i = tid; i < NBIN; i += FT) hist[i] = 0;
    if (tid == 0) sci[3] = 0;
    __syncthreads();
    for (int j = 0; j < 16; j++) {
        float s = sx[j*FT + tid];
        atomicAdd(&hist[binof(s, lo, invw)], 1);
    }
    __syncthreads();
    int hb[8]; int v = 0;
    #pragma unroll
    for (int j = 0; j < 8; j++) { hb[j] = hist[tid*8 + j]; v += hb[j]; }
    int incl = v;
    #pragma unroll
    for (int o = 1; o < 32; o <<= 1) {
        int x = __shfl_down_sync(0xffffffffu, incl, o);
        if (lane + o < 32) incl += x;
    }
    if (lane == 0) sw[warp] = incl;
    __syncthreads();
    if (warp == 0) {
        int x = (lane < NWARP) ? sw[lane] : 0;
        int incl2 = x;
        #pragma unroll
        for (int o = 1; o < 16; o <<= 1) {
            int y = __shfl_down_sync(0xffffffffu, incl2, o);
            if (lane + o < NWARP) incl2 += y;
        }
        if (lane < NWARP) sw[lane] = incl2 - x;
    }
    __syncthreads();
    int above = sw[warp] + (incl - v);
    #pragma unroll
    for (int j = 7; j >= 0; j--) {
        int c = hb[j];
        if (above < K && above + c >= K) {
            sci[0] = tid*8 + j; sci[1] = above; sci[2] = c;
        }
        above += c;
    }
    __syncthreads();
    const int critB = sci[0], aboveB = sci[1], cntB = sci[2];
    for (int j = 0; j < 16; j++) {
        float s = sx[j*FT + tid];
        if (binof(s, lo, invw) == critB) {
            int p = atomicAdd(&sci[3], 1);
            if (p < KLCAP) klist[p] = fmap(s);
        }
    }
    __syncthreads();
    const int m = min(cntB, KLCAP);
    const int Kp = K - aboveB;
    for (int e = tid; e < m; e += FT) {
        uint32_t ke = klist[e]; int gt = 0, eq = 0;
        for (int i = 0; i < m; i++) {
            uint32_t o = klist[i];
            gt += (o > ke); eq += (o == ke);
        }
        if (gt < Kp && gt + eq >= Kp) { sci[4] = (int)ke; sci[5] = Kp - gt; }
    }
    __syncthreads();
}

__device__ __forceinline__ int block_exscan512(int v, int* sw, int tid) {
    int lane = tid & 31, w = tid >> 5;
    int x = v;
    #pragma unroll
    for (int o = 1; o < 32; o <<= 1) {
        int y = __shfl_up_sync(0xffffffffu, x, o);
        if (lane >= o) x += y;
    }
    __syncthreads();
    if (lane == 31) sw[w] = x;
    __syncthreads();
    if (w == 0) {
        int s = (lane < NWARP) ? sw[lane] : 0;
        #pragma unroll
        for (int o = 1; o < 16; o <<= 1) {
            int y = __shfl_up_sync(0xffffffffu, s, o);
            if (lane >= o) s += y;
        }
        if (lane < NWARP) sw[lane] = s;
    }
    __syncthreads();
    int base = (w == 0) ? 0 : sw[w-1];
    return base + x - v;
}

// smem layout offsets (bytes)
#define SM_SX     0
#define SM_HIST   32768
#define SM_BAND   49152
#define SM_KLIST  53248
#define SM_MICRO  57344
#define SM_B1     57856
#define SM_W2     58368
#define SM_PP     58880
#define SM_SW     59904
#define SM_REDF   60032
#define SM_SCI    60224
#define SM_SCF    60256
#define SM_TOTAL  60416

// ---------------- kernel 3 (fused): selects + refine + micro-resolve -------
__global__ void __launch_bounds__(FT, 1)
fused_select(const float* __restrict__ tokens, const float* __restrict__ W1,
             const float* __restrict__ b1, const float* __restrict__ W2) {
    extern __shared__ unsigned char sm_raw[];
    float*    sx    = (float*)(sm_raw + SM_SX);
    int*      hist  = (int*)(sm_raw + SM_HIST);
    int*      band  = (int*)(sm_raw + SM_BAND);
    uint32_t* klist = (uint32_t*)(sm_raw + SM_KLIST);
    int*      micro = (int*)(sm_raw + SM_MICRO);
    float*    s_b1  = (float*)(sm_raw + SM_B1);
    float*    s_w2  = (float*)(sm_raw + SM_W2);
    float*    pp    = (float*)(sm_raw + SM_PP);
    int*      sw    = (int*)(sm_raw + SM_SW);
    float*    redf  = (float*)(sm_raw + SM_REDF);
    int*      sci   = (int*)(sm_raw + SM_SCI);
    float*    scf   = (float*)(sm_raw + SM_SCF);

    const int tid = threadIdx.x, warp = tid >> 5, lane = tid & 31;
    const int b = blockIdx.x;
    const int g = lane >> 2, t = lane & 3;

    if (tid < HID_) { s_b1[tid] = b1[tid]; s_w2[tid] = W2[tid]; }

    float mn = 1e30f, mx = -1e30f, ss = 0.0f;
    for (int j = 0; j < 16; j++) {
        int i = j*FT + tid;
        float s = g_scores[b*N_ + i];
        sx[i] = s;
        mn = fminf(mn, s); mx = fmaxf(mx, s); ss += s*s;
    }
    #pragma unroll
    for (int o = 16; o; o >>= 1) {
        mn = fminf(mn, __shfl_xor_sync(0xffffffffu, mn, o));
        mx = fmaxf(mx, __shfl_xor_sync(0xffffffffu, mx, o));
        ss += __shfl_xor_sync(0xffffffffu, ss, o);
    }
    if (lane == 0) { redf[warp] = mn; redf[16+warp] = mx; redf[32+warp] = ss; }
    __syncthreads();
    if (tid == 0) {
        float a = 1e30f, c = -1e30f, d = 0.0f;
        for (int w = 0; w < NWARP; w++) {
            a = fminf(a, redf[w]); c = fmaxf(c, redf[16+w]); d += redf[32+w];
        }
        float lo = a - 0.02f, hi = c + 0.02f;
        scf[0] = lo;
        scf[1] = (float)NBIN / (hi - lo + 1e-6f);
        scf[2] = 0.04f * sqrtf(d / (float)N_) + 1e-5f;
        sci[6] = 0; sci[7] = 0;
    }
    __syncthreads();
    const float lo = scf[0], invw = scf[1], delta = scf[2];

    exact_sel(sx, hist, sw, klist, sci, lo, invw, KEEP_);
    const float T1 = funmap((uint32_t)sci[4]);

    for (int j = 0; j < 16; j++) {
        int i = j*FT + tid;
        if (fabsf(sx[i] - T1) <= delta) {
            int p = atomicAdd(&sci[6], 1);
            if (p < BANDCAP) band[p] = i;
        }
    }
    __syncthreads();
    const int bcnt = min(sci[6], BANDCAP);

    // in-CTA split-bf16 mma refine (2-warp teams per 16-row tile)
    {
        const int ntiles = (bcnt + 15) >> 4;
        const int nrounds = (ntiles + 7) >> 3;
        const int team = warp >> 1, sub = warp & 1;
        for (int rd = 0; rd < nrounds; rd++) {
            const int tile = rd*8 + team;
            if (tile < ntiles) {
                const int base = tile*16;
                const int nrows = min(16, bcnt - base);
                const int e0 = base + ((g < nrows) ? g : 0);
                const int e1 = base + ((g + 8 < nrows) ? g + 8 : 0);
                const int r0 = band[e0], r1 = band[e1];
                const float* A0 = tokens + ((long long)(b*N_ + r0)) * C_;
                const float* A1 = tokens + ((long long)(b*N_ + r1)) * C_;

                float acc[8][4];
                #pragma unroll
                for (int n2 = 0; n2 < 8; n2++)
                    #pragma unroll
                    for (int q = 0; q < 4; q++) acc[n2][q] = 0.0f;

                const uint4* Bf = g_w1frag4 + lane + sub*(8*32);
                #pragma unroll 2
                for (int kt = 0; kt < 16; kt++) {
                    const int col = kt*16 + t*2;
                    uint32_t aH[4], aL[4];
                    aH[0] = split2(*(const float2*)(A0 + col),     aL[0]);
                    aH[1] = split2(*(const float2*)(A1 + col),     aL[1]);
                    aH[2] = split2(*(const float2*)(A0 + col + 8), aL[2]);
                    aH[3] = split2(*(const float2*)(A1 + col + 8), aL[3]);
                    const uint4* bp = Bf + kt*(16*32);
                    #pragma unroll
                    for (int n2 = 0; n2 < 8; n2++) {
                        uint4 bb = bp[n2*32];
                        mma16816(acc[n2], aH, bb.x, bb.y);
                        mma16816(acc[n2], aH, bb.z, bb.w);
                        mma16816(acc[n2], aL, bb.x, bb.y);
                    }
                }
                float p0 = 0.0f, p1 = 0.0f;
                #pragma unroll
                for (int n2 = 0; n2 < 8; n2++) {
                    int c0 = (sub*8 + n2)*8 + t*2, c1 = c0 + 1;
                    p0 += gelu_exact(acc[n2][0] + s_b1[c0]) * s_w2[c0];
                    p0 += gelu_exact(acc[n2][1] + s_b1[c1]) * s_w2[c1];
                    p1 += gelu_exact(acc[n2][2] + s_b1[c0]) * s_w2[c0];
                    p1 += gelu_exact(acc[n2][3] + s_b1[c1]) * s_w2[c1];
                }
                p0 += __shfl_xor_sync(0xffffffffu, p0, 1);
                p0 += __shfl_xor_sync(0xffffffffu, p0, 2);
                p1 += __shfl_xor_sync(0xffffffffu, p1, 1);
                p1 += __shfl_xor_sync(0xffffffffu, p1, 2);
                if (t == 0) { pp[warp*16 + g] = p0; pp[warp*16 + 8 + g] = p1; }
            }
            __syncthreads();
            if (tile < ntiles && (warp & 1) == 0 && t == 0) {
                const int base = tile*16;
                const int nrows = min(16, bcnt - base);
                if (g < nrows)
                    sx[band[base + g]] = pp[warp*16 + g] + pp[(warp+1)*16 + g];
                if (g + 8 < nrows)
                    sx[band[base + 8 + g]] = pp[warp*16 + 8 + g] + pp[(warp+1)*16 + 8 + g];
            }
            __syncthreads();
        }
    }

    exact_sel(sx, hist, sw, klist, sci, lo, invw, KEEP_);
    const float T2 = funmap((uint32_t)sci[4]);

    for (int j = 0; j < 16; j++) {
        int i = j*FT + tid;
        if (fabsf(sx[i] - T2) <= 3e-4f) {
            int p = atomicAdd(&sci[7], 1);
            if (p < MICROCAP) micro[p] = i;
        }
    }
    __syncthreads();
    const int mc = min(sci[7], MICROCAP);

    for (int e = warp; e < mc; e += NWARP) {
        const int r = micro[e];
        const float* X = tokens + ((long long)(b*N_ + r)) * C_;
        float s4[4], cc[4];
        #pragma unroll
        for (int q = 0; q < 4; q++) { s4[q] = 0.0f; cc[q] = 0.0f; }
        #pragma unroll 4
        for (int k = 0; k < C_; k++) {
            float4 wv = __ldg((const float4*)(W1 + k*HID_) + lane);
            float wq[4] = {wv.x, wv.y, wv.z, wv.w};
            float xk = __ldg(X + k);
            #pragma unroll
            for (int q = 0; q < 4; q++) {
                float p  = xk * wq[q];
                float er = fmaf(xk, wq[q], -p);
                float tn = s4[q] + p;
                float z  = tn - s4[q];
                float e2 = (s4[q] - (tn - z)) + (p - z);
                s4[q] = tn;
                cc[q] += er + e2;
            }
        }
        double sd = 0.0;
        #pragma unroll
        for (int q = 0; q < 4; q++) {
            int h = lane*4 + q;
            double hv = (double)s4[q] + (double)cc[q] + (double)b1[h];
            double gl = 0.5 * hv * (1.0 + erf(hv * 0.70710678118654752440));
            sd += gl * (double)W2[h];
        }
        #pragma unroll
        for (int o = 16; o; o >>= 1)
            sd += __shfl_xor_sync(0xffffffffu, sd, o);
        if (lane == 0) sx[r] = (float)sd;
    }
    __syncthreads();

    exact_sel(sx, hist, sw, klist, sci, lo, invw, KEEP_);
    const uint32_t T = (uint32_t)sci[4];
    const int need_eq = sci[5];

    const int base_i = tid * 16;
    uint32_t kv[16];
    int eqc = 0;
    #pragma unroll
    for (int j = 0; j < 16; j++) {
        kv[j] = fmap(sx[base_i + j]);
        eqc += (kv[j] == T);
    }
    int e = block_exscan512(eqc, sw, tid);
    int keepc = 0; uint32_t kpmask = 0;
    #pragma unroll
    for (int j = 0; j < 16; j++) {
        bool k = (kv[j] > T);
        if (kv[j] == T) { k = (e < need_eq); e++; }
        if (k) { kpmask |= (1u << j); keepc++; }
    }
    int pos = block_exscan512(keepc, sw, tid);
    #pragma unroll
    for (int j = 0; j < 16; j++) {
        if (kpmask & (1u << j)) { g_idx[b*KEEP_ + pos] = base_i + j; pos++; }
    }
}

// ---------------- kernel 4: gather pruned tokens + emit indices ------------
__global__ void __launch_bounds__(512)
gather_rows(const float* __restrict__ tokens, float* __restrict__ out,
            int write_idx) {
    int rid = blockIdx.x * 16 + (threadIdx.x >> 5);
    if (rid >= B_*KEEP_) return;
    int lane = threadIdx.x & 31;
    int b = rid / KEEP_;
    int idx = g_idx[rid];
    const float4* s = (const float4*)(tokens + ((long long)(b*N_ + idx)) * C_);
    float4* d = (float4*)(out + (long long)rid * C_);
    d[lane]      = s[lane];
    d[lane + 32] = s[lane + 32];
    if (write_idx && lane == 0)
        out[(long long)B_*KEEP_*C_ + rid] = (float)idx;
}

// ---------------- launch ----------------------------------------------------
extern "C" void kernel_launch(void* const* d_in, const int* in_sizes, int n_in,
                              void* d_out, int out_size) {
    const float* tokens = (const float*)d_in[0];
    const float* W1     = (const float*)d_in[1];
    const float* b1     = (const float*)d_in[2];
    const float* W2     = (const float*)d_in[3];
    // b2 shifts all scores equally -> selection-invariant; not in output.

    prep_w1<<<32, 256>>>(W1);

    gemm_scores<<<M_/256, 256>>>(tokens, b1, W2);

    cudaFuncSetAttribute(fused_select,
                         cudaFuncAttributeMaxDynamicSharedMemorySize, SM_TOTAL);
    fused_select<<<B_, FT, SM_TOTAL>>>(tokens, W1, b1, W2);

    long long prunedN = (long long)B_ * KEEP_ * C_;
    int wi = ((long long)out_size >= prunedN + (long long)B_*KEEP_) ? 1 : 0;
    gather_rows<<<(B_*KEEP_ + 15)/16, 512>>>(tokens, (float*)d_out, wi);
}

// round 13
// speedup vs baseline: 1.0979x; 1.0979x over previous
#include <cuda_runtime.h>
#include <cuda_bf16.h>
#include <cstdint>
#include <math.h>

#define B_    16
#define N_    8192
#define C_    256
#define HID_  128
#define KEEP_ 5734
#define M_    (B_*N_)   // 131072 rows
#define FT    512       // fused kernel threads
#define NWARP (FT/32)   // 16
#define NBIN  4096
#define BANDCAP  1024
#define MICROCAP 128

// ---------------- scratch (device globals; no allocation allowed) ----------
__device__ float g_scores[M_];
__device__ int   g_idx[B_*KEEP_];
// W1 fragments, mma.m16n8k16 B-operand layout:
// hi-only (screen): [kt][nt][lane] uint2 ; hi+lo (refine): uint4
__device__ __align__(16) uint2 g_w1fragH[16*16*32];
__device__ __align__(16) uint4 g_w1frag4[16*16*32];

// ---------------- helpers ---------------------------------------------------
__device__ __forceinline__ uint32_t pack2(__nv_bfloat16 lo, __nv_bfloat16 hi) {
    uint16_t a = __bfloat16_as_ushort(lo);
    uint16_t b = __bfloat16_as_ushort(hi);
    return ((uint32_t)b << 16) | (uint32_t)a;
}
__device__ __forceinline__ uint32_t cvt2(float2 f) {
    __nv_bfloat162 h = __float22bfloat162_rn(f);
    return *(uint32_t*)&h;
}
__device__ __forceinline__ uint32_t split2(float2 f, uint32_t& lo) {
    __nv_bfloat16 hx = __float2bfloat16_rn(f.x);
    __nv_bfloat16 hy = __float2bfloat16_rn(f.y);
    lo = pack2(__float2bfloat16_rn(f.x - __bfloat162float(hx)),
               __float2bfloat16_rn(f.y - __bfloat162float(hy)));
    return pack2(hx, hy);
}
__device__ __forceinline__ void mma16816(float* c, const uint32_t* a,
                                         uint32_t b0, uint32_t b1) {
    asm volatile(
        "mma.sync.aligned.m16n8k16.row.col.f32.bf16.bf16.f32 "
        "{%0,%1,%2,%3},{%4,%5,%6,%7},{%8,%9},{%0,%1,%2,%3};\n"
        : "+f"(c[0]), "+f"(c[1]), "+f"(c[2]), "+f"(c[3])
        : "r"(a[0]), "r"(a[1]), "r"(a[2]), "r"(a[3]), "r"(b0), "r"(b1));
}
__device__ __forceinline__ float gelu_exact(float x) {
    return 0.5f * x * (1.0f + erff(x * 0.70710678118654752f));
}
__device__ __forceinline__ uint32_t fmap(float f) {
    uint32_t v = __float_as_uint(f);
    return (v & 0x80000000u) ? ~v : (v | 0x80000000u);
}
__device__ __forceinline__ int binof(float s, float lo, float invw) {
    int b = (int)((s - lo) * invw);
    return min(max(b, 0), NBIN - 1);
}

// ---------------- kernel 1: pack W1 into bf16 mma fragments ----------------
__global__ void prep_w1(const float* __restrict__ W1) {
    int id = blockIdx.x * blockDim.x + threadIdx.x;   // 8192 total
    if (id >= 16*16*32) return;
    int lane = id & 31;
    int kt   = id >> 9;
    int t = lane & 3, g = lane >> 2;
    int nt = (id >> 5) & 15;
    int n  = nt*8 + g;
    int k0 = kt*16 + t*2;
    float w00 = W1[k0*HID_ + n],     w01 = W1[(k0+1)*HID_ + n];
    float w10 = W1[(k0+8)*HID_ + n], w11 = W1[(k0+9)*HID_ + n];
    __nv_bfloat16 h00 = __float2bfloat16_rn(w00), h01 = __float2bfloat16_rn(w01);
    __nv_bfloat16 h10 = __float2bfloat16_rn(w10), h11 = __float2bfloat16_rn(w11);
    uint4 v;
    v.x = pack2(h00, h01);
    v.y = pack2(h10, h11);
    v.z = pack2(__float2bfloat16_rn(w00 - __bfloat162float(h00)),
                __float2bfloat16_rn(w01 - __bfloat162float(h01)));
    v.w = pack2(__float2bfloat16_rn(w10 - __bfloat162float(h10)),
                __float2bfloat16_rn(w11 - __bfloat162float(h11)));
    g_w1frag4[id] = v;
    g_w1fragH[id] = make_uint2(v.x, v.y);
}

// ---------------- kernel 2: screen: fc1(bf16 mma) -> GELU -> fc2 -----------
// (R9 version: 16 rows/warp, 2 CTAs/SM)
__global__ void __launch_bounds__(256, 2)
gemm_scores(const float* __restrict__ tokens,
            const float* __restrict__ b1,
            const float* __restrict__ W2) {
    __shared__ float s_b1[HID_], s_w2[HID_];
    const int tid = threadIdx.x;
    if (tid < HID_) { s_b1[tid] = b1[tid]; s_w2[tid] = W2[tid]; }
    __syncthreads();

    const int warp = tid >> 5, lane = tid & 31;
    const int g = lane >> 2, t = lane & 3;
    const long long row0 = (long long)(blockIdx.x * 8 + warp) * 16;
    const float* A0 = tokens + row0 * C_;

    float acc[16][4];
    #pragma unroll
    for (int n = 0; n < 16; n++)
        #pragma unroll
        for (int q = 0; q < 4; q++) acc[n][q] = 0.0f;

    const uint2* Bf = g_w1fragH + lane;

    #pragma unroll 4
    for (int kt = 0; kt < 16; kt++) {
        const int col = kt*16 + t*2;
        uint32_t a[4];
        a[0] = cvt2(*(const float2*)(A0 + (g)     * C_ + col));
        a[1] = cvt2(*(const float2*)(A0 + (g + 8) * C_ + col));
        a[2] = cvt2(*(const float2*)(A0 + (g)     * C_ + col + 8));
        a[3] = cvt2(*(const float2*)(A0 + (g + 8) * C_ + col + 8));

        const uint2* bp = Bf + kt*16*32;
        #pragma unroll
        for (int nt = 0; nt < 16; nt++) {
            uint2 bb = bp[nt*32];
            mma16816(acc[nt], a, bb.x, bb.y);
        }
    }

    float p0 = 0.0f, p1 = 0.0f;
    #pragma unroll
    for (int nt = 0; nt < 16; nt++) {
        int c0 = nt*8 + t*2, c1 = c0 + 1;
        p0 += gelu_exact(acc[nt][0] + s_b1[c0]) * s_w2[c0];
        p0 += gelu_exact(acc[nt][1] + s_b1[c1]) * s_w2[c1];
        p1 += gelu_exact(acc[nt][2] + s_b1[c0]) * s_w2[c0];
        p1 += gelu_exact(acc[nt][3] + s_b1[c1]) * s_w2[c1];
    }
    p0 += __shfl_xor_sync(0xffffffffu, p0, 1);
    p0 += __shfl_xor_sync(0xffffffffu, p0, 2);
    p1 += __shfl_xor_sync(0xffffffffu, p1, 1);
    p1 += __shfl_xor_sync(0xffffffffu, p1, 2);
    if (t == 0) {
        g_scores[row0 + g]     = p0;
        g_scores[row0 + 8 + g] = p1;
    }
}

// ---------------- block-wide exclusive scan (512 thr) ----------------------
__device__ __forceinline__ int block_exscan512(int v, int* sw, int tid) {
    int lane = tid & 31, w = tid >> 5;
    int x = v;
    #pragma unroll
    for (int o = 1; o < 32; o <<= 1) {
        int y = __shfl_up_sync(0xffffffffu, x, o);
        if (lane >= o) x += y;
    }
    __syncthreads();
    if (lane == 31) sw[w] = x;
    __syncthreads();
    if (w == 0) {
        int s = (lane < NWARP) ? sw[lane] : 0;
        #pragma unroll
        for (int o = 1; o < 16; o <<= 1) {
            int y = __shfl_up_sync(0xffffffffu, s, o);
            if (lane >= o) s += y;
        }
        if (lane < NWARP) sw[lane] = s;
    }
    __syncthreads();
    int base = (w == 0) ? 0 : sw[w-1];
    return base + x - v;
}

// exact K'-th select over a small key array (<= BANDCAP), O(m^2)/FT.
// sci[4]=T(uint key, init 0xFFFFFFFF), sci[5]=need_eq
__device__ void band_sel(const uint32_t* rbk, int bcnt, int K2, int* sci) {
    const int tid = threadIdx.x;
    if (tid == 0) { sci[4] = (int)0xFFFFFFFFu; sci[5] = 0; }
    __syncthreads();
    if (K2 > 0) {
        for (int e = tid; e < bcnt; e += FT) {
            uint32_t ke = rbk[e]; int gt = 0, eq = 0;
            for (int i = 0; i < bcnt; i++) {
                uint32_t o = rbk[i];
                gt += (o > ke); eq += (o == ke);
            }
            if (gt < K2 && gt + eq >= K2) { sci[4] = (int)ke; sci[5] = K2 - gt; }
        }
    }
    __syncthreads();
}

// smem layout offsets (bytes)
#define SM_SX     0        // float[8192]  32768
#define SM_HIST   32768    // int[4096]    16384 (flags overlay: 8192 bytes)
#define SM_BAND   49152    // int[1024]    4096
#define SM_RBK    53248    // uint[1024]   4096
#define SM_MICRO  57344    // int[128]     512
#define SM_B1     57856
#define SM_W2     58368
#define SM_PP     58880    // float[256]
#define SM_SW     59904
#define SM_REDF   60032
#define SM_SCI    60224
#define SM_SCF    60256
#define SM_TOTAL  60416

// ---------------- kernel 3 (fused v2): approx sel -> band-only exact -------
__global__ void __launch_bounds__(FT, 1)
fused_select(const float* __restrict__ tokens, const float* __restrict__ W1,
             const float* __restrict__ b1, const float* __restrict__ W2) {
    extern __shared__ unsigned char sm_raw[];
    float*         sx    = (float*)(sm_raw + SM_SX);
    int*           hist  = (int*)(sm_raw + SM_HIST);
    unsigned char* flags = (unsigned char*)(sm_raw + SM_HIST);  // overlay
    int*           band  = (int*)(sm_raw + SM_BAND);
    uint32_t*      rbk   = (uint32_t*)(sm_raw + SM_RBK);
    int*           micro = (int*)(sm_raw + SM_MICRO);
    float*         s_b1  = (float*)(sm_raw + SM_B1);
    float*         s_w2  = (float*)(sm_raw + SM_W2);
    float*         pp    = (float*)(sm_raw + SM_PP);
    int*           sw    = (int*)(sm_raw + SM_SW);
    float*         redf  = (float*)(sm_raw + SM_REDF);
    int*           sci   = (int*)(sm_raw + SM_SCI);
    float*         scf   = (float*)(sm_raw + SM_SCF);

    const int tid = threadIdx.x, warp = tid >> 5, lane = tid & 31;
    const int b = blockIdx.x;
    const int g = lane >> 2, t = lane & 3;

    if (tid < HID_) { s_b1[tid] = b1[tid]; s_w2[tid] = W2[tid]; }

    // load scores + min/max/sumsq reduce; zero histogram
    for (int i = tid; i < NBIN; i += FT) hist[i] = 0;
    float mn = 1e30f, mx = -1e30f, ss = 0.0f;
    for (int j = 0; j < 16; j++) {
        int i = j*FT + tid;
        float s = g_scores[b*N_ + i];
        sx[i] = s;
        mn = fminf(mn, s); mx = fmaxf(mx, s); ss += s*s;
    }
    #pragma unroll
    for (int o = 16; o; o >>= 1) {
        mn = fminf(mn, __shfl_xor_sync(0xffffffffu, mn, o));
        mx = fmaxf(mx, __shfl_xor_sync(0xffffffffu, mx, o));
        ss += __shfl_xor_sync(0xffffffffu, ss, o);
    }
    if (lane == 0) { redf[warp] = mn; redf[16+warp] = mx; redf[32+warp] = ss; }
    __syncthreads();
    if (tid == 0) {
        float a = 1e30f, c = -1e30f, d = 0.0f;
        for (int w = 0; w < NWARP; w++) {
            a = fminf(a, redf[w]); c = fmaxf(c, redf[16+w]); d += redf[32+w];
        }
        float lo = a - 0.02f, hi = c + 0.02f;
        scf[0] = lo;
        scf[1] = (float)NBIN / (hi - lo + 1e-6f);
        scf[2] = 0.04f * sqrtf(d / (float)N_) + 1e-5f;   // delta
        sci[6] = 0;  // bcnt
        sci[7] = 0;  // Kin
        sci[3] = 0;  // micro cnt
    }
    __syncthreads();
    const float lo = scf[0], invw = scf[1], delta = scf[2];

    // ---- sel1 (approx): histogram -> critical bin lower edge T1a ----------
    for (int j = 0; j < 16; j++)
        atomicAdd(&hist[binof(sx[j*FT + tid], lo, invw)], 1);
    __syncthreads();
    {
        int hb[8]; int v = 0;
        #pragma unroll
        for (int j = 0; j < 8; j++) { hb[j] = hist[tid*8 + j]; v += hb[j]; }
        int incl = v;
        #pragma unroll
        for (int o = 1; o < 32; o <<= 1) {
            int x = __shfl_down_sync(0xffffffffu, incl, o);
            if (lane + o < 32) incl += x;
        }
        if (lane == 0) sw[warp] = incl;
        __syncthreads();
        if (warp == 0) {
            int x = (lane < NWARP) ? sw[lane] : 0;
            int incl2 = x;
            #pragma unroll
            for (int o = 1; o < 16; o <<= 1) {
                int y = __shfl_down_sync(0xffffffffu, incl2, o);
                if (lane + o < NWARP) incl2 += y;
            }
            if (lane < NWARP) sw[lane] = incl2 - x;
        }
        __syncthreads();
        int above = sw[warp] + (incl - v);
        #pragma unroll
        for (int j = 7; j >= 0; j--) {
            int c = hb[j];
            if (above < KEEP_ && above + c >= KEEP_) sci[0] = tid*8 + j;
            above += c;
        }
        __syncthreads();
    }
    const float T1a = lo + (float)sci[0] / invw;   // bin lower edge
    const float cutTop = T1a + delta;
    const float cutBot = T1a - delta;
    __syncthreads();

    // ---- band collect + Kin count (flags overlay hist region) -------------
    for (int i = tid; i < 2048; i += FT) ((int*)flags)[i] = 0;
    __syncthreads();
    for (int j = 0; j < 16; j++) {
        int i = j*FT + tid;
        float s = sx[i];
        if (s > cutTop) {
            atomicAdd(&sci[7], 1);
        } else if (s >= cutBot) {
            int p = atomicAdd(&sci[6], 1);
            if (p < BANDCAP) { band[p] = i; flags[i] = 1; }
        }
    }
    __syncthreads();
    const int bcnt = min(sci[6], BANDCAP);
    const int K2 = KEEP_ - sci[7];

    // ---- in-CTA split-bf16 mma refine of band rows (2-warp teams) ---------
    {
        const int ntiles = (bcnt + 15) >> 4;
        const int nrounds = (ntiles + 7) >> 3;
        const int team = warp >> 1, sub = warp & 1;
        for (int rd = 0; rd < nrounds; rd++) {
            const int tile = rd*8 + team;
            if (tile < ntiles) {
                const int base = tile*16;
                const int nrows = min(16, bcnt - base);
                const int e0 = base + ((g < nrows) ? g : 0);
                const int e1 = base + ((g + 8 < nrows) ? g + 8 : 0);
                const int r0 = band[e0], r1 = band[e1];
                const float* A0 = tokens + ((long long)(b*N_ + r0)) * C_;
                const float* A1 = tokens + ((long long)(b*N_ + r1)) * C_;

                float acc[8][4];
                #pragma unroll
                for (int n2 = 0; n2 < 8; n2++)
                    #pragma unroll
                    for (int q = 0; q < 4; q++) acc[n2][q] = 0.0f;

                const uint4* Bf = g_w1frag4 + lane + sub*(8*32);
                #pragma unroll 2
                for (int kt = 0; kt < 16; kt++) {
                    const int col = kt*16 + t*2;
                    uint32_t aH[4], aL[4];
                    aH[0] = split2(*(const float2*)(A0 + col),     aL[0]);
                    aH[1] = split2(*(const float2*)(A1 + col),     aL[1]);
                    aH[2] = split2(*(const float2*)(A0 + col + 8), aL[2]);
                    aH[3] = split2(*(const float2*)(A1 + col + 8), aL[3]);
                    const uint4* bp = Bf + kt*(16*32);
                    #pragma unroll
                    for (int n2 = 0; n2 < 8; n2++) {
                        uint4 bb = bp[n2*32];
                        mma16816(acc[n2], aH, bb.x, bb.y);
                        mma16816(acc[n2], aH, bb.z, bb.w);
                        mma16816(acc[n2], aL, bb.x, bb.y);
                    }
                }
                float p0 = 0.0f, p1 = 0.0f;
                #pragma unroll
                for (int n2 = 0; n2 < 8; n2++) {
                    int c0 = (sub*8 + n2)*8 + t*2, c1 = c0 + 1;
                    p0 += gelu_exact(acc[n2][0] + s_b1[c0]) * s_w2[c0];
                    p0 += gelu_exact(acc[n2][1] + s_b1[c1]) * s_w2[c1];
                    p1 += gelu_exact(acc[n2][2] + s_b1[c0]) * s_w2[c0];
                    p1 += gelu_exact(acc[n2][3] + s_b1[c1]) * s_w2[c1];
                }
                p0 += __shfl_xor_sync(0xffffffffu, p0, 1);
                p0 += __shfl_xor_sync(0xffffffffu, p0, 2);
                p1 += __shfl_xor_sync(0xffffffffu, p1, 1);
                p1 += __shfl_xor_sync(0xffffffffu, p1, 2);
                if (t == 0) { pp[warp*16 + g] = p0; pp[warp*16 + 8 + g] = p1; }
            }
            __syncthreads();
            if (tile < ntiles && (warp & 1) == 0 && t == 0) {
                const int base = tile*16;
                const int nrows = min(16, bcnt - base);
                if (g < nrows)
                    sx[band[base + g]] = pp[warp*16 + g] + pp[(warp+1)*16 + g];
                if (g + 8 < nrows)
                    sx[band[base + 8 + g]] = pp[warp*16 + 8 + g] + pp[(warp+1)*16 + 8 + g];
            }
            __syncthreads();
        }
    }

    // ---- sel2: exact K2-th among band (refined) ----------------------------
    for (int e = tid; e < bcnt; e += FT) rbk[e] = fmap(sx[band[e]]);
    __syncthreads();
    band_sel(rbk, bcnt, K2, sci);
    {
        uint32_t T2k = (uint32_t)sci[4];
        float T2f = (T2k == 0xFFFFFFFFu) ? 1e30f :
            ((T2k & 0x80000000u) ? __uint_as_float(T2k ^ 0x80000000u)
                                 : __uint_as_float(~T2k));
        // micro collect among band rows
        for (int e = tid; e < bcnt; e += FT) {
            if (fabsf(sx[band[e]] - T2f) <= 3e-4f) {
                int p = atomicAdd(&sci[3], 1);
                if (p < MICROCAP) micro[p] = band[e];
            }
        }
    }
    __syncthreads();
    const int mc = min(sci[3], MICROCAP);

    // fp64-grade resolve of micro rows (one per warp)
    for (int e = warp; e < mc; e += NWARP) {
        const int r = micro[e];
        const float* X = tokens + ((long long)(b*N_ + r)) * C_;
        float s4[4], cc[4];
        #pragma unroll
        for (int q = 0; q < 4; q++) { s4[q] = 0.0f; cc[q] = 0.0f; }
        #pragma unroll 4
        for (int k = 0; k < C_; k++) {
            float4 wv = __ldg((const float4*)(W1 + k*HID_) + lane);
            float wq[4] = {wv.x, wv.y, wv.z, wv.w};
            float xk = __ldg(X + k);
            #pragma unroll
            for (int q = 0; q < 4; q++) {
                float p  = xk * wq[q];
                float er = fmaf(xk, wq[q], -p);
                float tn = s4[q] + p;
                float z  = tn - s4[q];
                float e2 = (s4[q] - (tn - z)) + (p - z);
                s4[q] = tn;
                cc[q] += er + e2;
            }
        }
        double sd = 0.0;
        #pragma unroll
        for (int q = 0; q < 4; q++) {
            int h = lane*4 + q;
            double hv = (double)s4[q] + (double)cc[q] + (double)b1[h];
            double gl = 0.5 * hv * (1.0 + erf(hv * 0.70710678118654752440));
            sd += gl * (double)W2[h];
        }
        #pragma unroll
        for (int o = 16; o; o >>= 1)
            sd += __shfl_xor_sync(0xffffffffu, sd, o);
        if (lane == 0) sx[r] = (float)sd;
    }
    __syncthreads();

    // ---- sel3: final exact K2-th among band (post-resolve) -----------------
    for (int e = tid; e < bcnt; e += FT) rbk[e] = fmap(sx[band[e]]);
    __syncthreads();
    band_sel(rbk, bcnt, K2, sci);
    const uint32_t T = (uint32_t)sci[4];
    const int need_eq = sci[5];

    // ---- emit indices (ascending index order) ------------------------------
    const int base_i = tid * 16;
    int eqc = 0;
    unsigned char isband[16];
    uint32_t kv[16];
    #pragma unroll
    for (int j = 0; j < 16; j++) {
        int i = base_i + j;
        isband[j] = flags[i];
        kv[j] = fmap(sx[i]);
        eqc += (isband[j] && kv[j] == T);
    }
    int e = block_exscan512(eqc, sw, tid);
    int keepc = 0; uint32_t kpmask = 0;
    #pragma unroll
    for (int j = 0; j < 16; j++) {
        bool k;
        if (isband[j]) {
            k = (kv[j] > T);
            if (kv[j] == T) { k = (e < need_eq); e++; }
        } else {
            k = (sx[base_i + j] > cutTop);
        }
        if (k) { kpmask |= (1u << j); keepc++; }
    }
    int pos = block_exscan512(keepc, sw, tid);
    #pragma unroll
    for (int j = 0; j < 16; j++) {
        if (kpmask & (1u << j)) { g_idx[b*KEEP_ + pos] = base_i + j; pos++; }
    }
}

// ---------------- kernel 4: gather pruned tokens + emit indices ------------
__global__ void __launch_bounds__(512)
gather_rows(const float* __restrict__ tokens, float* __restrict__ out,
            int write_idx) {
    int rid = blockIdx.x * 16 + (threadIdx.x >> 5);
    if (rid >= B_*KEEP_) return;
    int lane = threadIdx.x & 31;
    int b = rid / KEEP_;
    int idx = g_idx[rid];
    const float4* s = (const float4*)(tokens + ((long long)(b*N_ + idx)) * C_);
    float4* d = (float4*)(out + (long long)rid * C_);
    d[lane]      = s[lane];
    d[lane + 32] = s[lane + 32];
    if (write_idx && lane == 0)
        out[(long long)B_*KEEP_*C_ + rid] = (float)idx;
}

// ---------------- launch ----------------------------------------------------
extern "C" void kernel_launch(void* const* d_in, const int* in_sizes, int n_in,
                              void* d_out, int out_size) {
    const float* tokens = (const float*)d_in[0];
    const float* W1     = (const float*)d_in[1];
    const float* b1     = (const float*)d_in[2];
    const float* W2     = (const float*)d_in[3];
    // b2 shifts all scores equally -> selection-invariant; not in output.

    prep_w1<<<32, 256>>>(W1);

    gemm_scores<<<M_/128, 256>>>(tokens, b1, W2);

    cudaFuncSetAttribute(fused_select,
                         cudaFuncAttributeMaxDynamicSharedMemorySize, SM_TOTAL);
    fused_select<<<B_, FT, SM_TOTAL>>>(tokens, W1, b1, W2);

    long long prunedN = (long long)B_ * KEEP_ * C_;
    int wi = ((long long)out_size >= prunedN + (long long)B_*KEEP_) ? 1 : 0;
    gather_rows<<<(B_*KEEP_ + 15)/16, 512>>>(tokens, (float*)d_out, wi);
}